// round 15
// baseline (speedup 1.0000x reference)
#include <cuda_runtime.h>
#include <cuda_fp16.h>
#include <cstdint>

#define NB    2048
#define ND    40960
#define NBASE 288
#define NH    576     // 2*NBASE
#define NA0   144
#define NMOVE 4096
#define KP    736     // padded act K: [a0(144) pad(16) base(576)]
#define AOFF  160     // base starts here
#define NSTG  23      // K chunks of 32 halfs (64B rows)
#define MAXNZ 512

// -------- device scratch (no allocations allowed) --------
__device__ __half g_WTw_h[(size_t)ND * NBASE]; // W_w^T  [D, 288] fp16
__device__ __half g_WTb_h[(size_t)ND * NBASE]; // W_b^T  [D, 288] fp16
__device__ float  g_WTv0[NH * 32];             // W_v0^T [576, 32] fp32
__device__ float  g_base[(size_t)NB * NH];     // relu'd base, fp32
__device__ __half g_actA_h[(size_t)NB * KP];   // [relu(a0) | 0 | relu(base)] fp16
__device__ __half g_actB_h[(size_t)NMOVE * KP];// [W_a1 | 0 | W_as] fp16
__device__ int    g_nzcnt[NB * 2];
__device__ int    g_nzidx[(size_t)NB * 2 * MAXNZ];
__device__ int    g_a0done;    // a0 blocks done (reset in prep, used in fuse)
__device__ int    g_scandone;  // scan blocks done (reset in fuse, used in prep)
__device__ int    g_transdone; // transpose blocks done (reset in fuse, used in prep)

#define CP16(dst, src) asm volatile("cp.async.cg.shared.global [%0], [%1], 16;" :: "r"(dst), "l"(src))
#define CPCOMMIT()     asm volatile("cp.async.commit_group;")
#define CPWAIT(n)      asm volatile("cp.async.wait_group %0;" :: "n"(n))
#define LDSM4(R, addr) asm volatile( \
    "ldmatrix.sync.aligned.m8n8.x4.shared.b16 {%0,%1,%2,%3}, [%4];" \
    : "=r"((R)[0]), "=r"((R)[1]), "=r"((R)[2]), "=r"((R)[3]) : "r"(addr))

// ========= mega prep kernel: scan + transposes + GATHER + bprep ===========
// Block ranges (256 threads each):
//   [0, 4096)          : mask scan (indices only — nonzeros are exactly 1.0)
//   [4096, 27136)      : transpose W_w / W_b -> fp16 (counted)
//   [27136, 31232)     : gather (spins on scan+transpose counters)
//   [31232, 35328)     : bprep (g_actB_h)
//   [35328, 35346)     : W_v0 transpose (fp32)
#define NSCAN   (NB * 2)
#define NTRB    ((ND / 32) * (NBASE / 32))     // 11520 per matrix
#define GA_BID0 (NSCAN + 2 * NTRB)             // 27136
#define BP_BID0 (GA_BID0 + NSCAN)              // 31232
#define WV_BID0 (BP_BID0 + NMOVE)              // 35328
#define PREP_BLOCKS (WV_BID0 + NH / 32)        // 35346

#define CHECKI(vv, uu) do { \
    if ((vv).x != 0.0f) { int p = atomicAdd(s_cnt, 1); if (p < MAXNZ) s_idx[p] = 4*(uu)+0; } \
    if ((vv).y != 0.0f) { int p = atomicAdd(s_cnt, 1); if (p < MAXNZ) s_idx[p] = 4*(uu)+1; } \
    if ((vv).z != 0.0f) { int p = atomicAdd(s_cnt, 1); if (p < MAXNZ) s_idx[p] = 4*(uu)+2; } \
    if ((vv).w != 0.0f) { int p = atomicAdd(s_cnt, 1); if (p < MAXNZ) s_idx[p] = 4*(uu)+3; } \
} while (0)

__global__ __launch_bounds__(256) void prep_kernel(
    const float* __restrict__ white, const float* __restrict__ black,
    const float* __restrict__ W_w,   const float* __restrict__ W_b,
    const float* __restrict__ W_v0,
    const float* __restrict__ W_a1,  const float* __restrict__ W_as,
    const float* __restrict__ pov,
    const float* __restrict__ b_w,   const float* __restrict__ b_b)
{
    __shared__ __align__(16) char shbuf[4352];
    int bi = blockIdx.x;
    int t  = threadIdx.x;
    if (bi == 0 && t == 0) g_a0done = 0;    // reset for this launch's fuse

    if (bi < NSCAN) {
        // ---- mask scan: 4 independent streaming loads in flight ----
        int* s_idx = (int*)shbuf;
        int* s_cnt = (int*)(shbuf + 2048);
        int b = bi >> 1, h = bi & 1;
        if (t == 0) *s_cnt = 0;
        __syncthreads();
        const float* src = h ? black : white;
        const float4* row = reinterpret_cast<const float4*>(src + (size_t)b * ND);
        #pragma unroll 1
        for (int u = t; u < ND / 4; u += 1024) {   // 10240 = 10 * 1024
            float4 v0 = __ldcs(&row[u]);
            float4 v1 = __ldcs(&row[u + 256]);
            float4 v2 = __ldcs(&row[u + 512]);
            float4 v3 = __ldcs(&row[u + 768]);
            CHECKI(v0, u);
            CHECKI(v1, u + 256);
            CHECKI(v2, u + 512);
            CHECKI(v3, u + 768);
        }
        __syncthreads();
        int n = *s_cnt;
        if (n > MAXNZ) n = MAXNZ;
        if (t == 0) g_nzcnt[bi] = n;
        for (int k = t; k < n; k += 256)
            g_nzidx[(size_t)bi * MAXNZ + k] = s_idx[k];
        __syncthreads();
        __threadfence();
        if (t == 0) atomicAdd(&g_scandone, 1);
    } else if (bi < GA_BID0) {
        // ---- big transposes fp32 -> fp16 (counted) ----
        int which = (bi - NSCAN) / NTRB;
        int idx   = (bi - NSCAN) % NTRB;
        int c0 = (idx % (ND / 32)) * 32;
        int r0 = (idx / (ND / 32)) * 32;
        const float* in = which ? W_b : W_w;
        __half* outp = which ? g_WTb_h : g_WTw_h;
        float (*tile)[33] = (float(*)[33])shbuf;
        int x = t & 31, y = t >> 5;
        #pragma unroll
        for (int yy = y; yy < 32; yy += 8)
            tile[yy][x] = in[(size_t)(r0 + yy) * ND + c0 + x];
        __syncthreads();
        #pragma unroll
        for (int yy = y; yy < 32; yy += 8)
            outp[(size_t)(c0 + yy) * NBASE + r0 + x] = __float2half(tile[x][yy]);
        __syncthreads();
        __threadfence();
        if (t == 0) atomicAdd(&g_transdone, 1);
    } else if (bi < BP_BID0) {
        // ---- gather: spin until scan + transposes complete ----
        int* s_idx = (int*)shbuf;
        int gi = bi - GA_BID0;
        if (t == 0) {
            while (atomicAdd(&g_scandone, 0)  < NSCAN)    { }
            while (atomicAdd(&g_transdone, 0) < 2 * NTRB) { }
        }
        __syncthreads();
        int b = gi >> 1, h = gi & 1;
        if (h == 0 && t < 16) g_actA_h[(size_t)b * KP + NA0 + t] = __float2half(0.0f);

        int n = g_nzcnt[gi];
        if (n > MAXNZ) n = MAXNZ;
        for (int k = t; k < n; k += 256)
            s_idx[k] = g_nzidx[(size_t)gi * MAXNZ + k];
        __syncthreads();

        const __half* WT = h ? g_WTb_h : g_WTw_h;
        float pv = pov[b];
        for (int i = t; i < NBASE; i += 256) {
            float acc = h ? b_b[i] : b_w[i];
            int k = 0;
            for (; k + 8 <= n; k += 8) {
                float p0 = __half2float(WT[(size_t)s_idx[k+0] * NBASE + i]);
                float p1 = __half2float(WT[(size_t)s_idx[k+1] * NBASE + i]);
                float p2 = __half2float(WT[(size_t)s_idx[k+2] * NBASE + i]);
                float p3 = __half2float(WT[(size_t)s_idx[k+3] * NBASE + i]);
                float p4 = __half2float(WT[(size_t)s_idx[k+4] * NBASE + i]);
                float p5 = __half2float(WT[(size_t)s_idx[k+5] * NBASE + i]);
                float p6 = __half2float(WT[(size_t)s_idx[k+6] * NBASE + i]);
                float p7 = __half2float(WT[(size_t)s_idx[k+7] * NBASE + i]);
                acc += ((p0 + p1) + (p2 + p3)) + ((p4 + p5) + (p6 + p7));
            }
            for (; k < n; k++)
                acc += __half2float(WT[(size_t)s_idx[k] * NBASE + i]);

            int pos;
            if (h == 0) pos = (pv > 0.5f) ? i : (NBASE + i);
            else        pos = (pv > 0.5f) ? (NBASE + i) : i;
            float r = fmaxf(acc, 0.0f);
            g_base[(size_t)b * NH + pos] = r;
            g_actA_h[(size_t)b * KP + AOFF + pos] = __float2half(r);
        }
    } else if (bi < WV_BID0) {
        // ---- bprep ----
        int n = bi - BP_BID0;
        for (int c2 = t; c2 < KP / 2; c2 += 256) {
            int c = c2 * 2;
            float v0 = 0.0f, v1 = 0.0f;
            if (c < NA0) {
                const float2 w = *(const float2*)&W_a1[(size_t)n * NA0 + c];
                v0 = w.x; v1 = w.y;
            } else if (c >= AOFF) {
                const float2 w = *(const float2*)&W_as[(size_t)n * NH + (c - AOFF)];
                v0 = w.x; v1 = w.y;
            }
            *(__half2*)&g_actB_h[(size_t)n * KP + c] = __floats2half2_rn(v0, v1);
        }
    } else {
        // ---- W_v0 transpose fp32 ----
        int idx = bi - WV_BID0;
        int c0 = idx * 32;
        float (*tile)[33] = (float(*)[33])shbuf;
        int x = t & 31, y = t >> 5;
        #pragma unroll
        for (int yy = y; yy < 32; yy += 8)
            tile[yy][x] = W_v0[(size_t)yy * NH + c0 + x];
        __syncthreads();
        #pragma unroll
        for (int yy = y; yy < 32; yy += 8)
            g_WTv0[(size_t)(c0 + yy) * 32 + x] = tile[x][yy];
    }
}

// ======== fused a0 + value + act (block-range dispatch, spin-sync) =========
// bids [0,96): a0   [96,352): value   [352,1376): act (flattened 32n x 32m)
// act K order: base chunks first (18), a0 chunks last (5) — spin on g_a0done.
#define A0_BLOCKS  96
#define VAL_BLOCKS 256
#define ACT_BID0   (A0_BLOCKS + VAL_BLOCKS)
#define ABUF   (64 * 80)
#define BBUF   (128 * 80)
#define NRING  4
#define SM_FUSE (NRING * (ABUF + BBUF) + 512)   // 61952 bytes

__device__ __forceinline__ int act_koff(int s) {    // stage -> half offset
    return (s < 18) ? (AOFF + s * 32) : ((s - 18) * 32);
}

__global__ __launch_bounds__(256, 3) void fuse_kernel(
    const float* __restrict__ W_a0, const float* __restrict__ b_a0,
    const float* __restrict__ b_v0,
    const float* __restrict__ W_v1, const float* __restrict__ b_v1,
    const float* __restrict__ W_v2, const float* __restrict__ b_v2,
    const float* __restrict__ W_vs, const float* __restrict__ b_vs,
    const float* __restrict__ b_a1, const float* __restrict__ b_as,
    float* __restrict__ out)
{
    extern __shared__ __align__(16) char smem[];
    int t = threadIdx.x;
    // reset prep's counters for the NEXT launch (no fuse block reads them)
    if (blockIdx.x == 0 && t == 0) {
        atomicExch(&g_scandone, 0);
        atomicExch(&g_transdone, 0);
    }

    if (blockIdx.x < A0_BLOCKS) {
        // ---------------- a0 = relu(base @ W_a0^T + b_a0) -> fp16 ----------
        float (*sA)[64] = (float(*)[64])smem;
        float (*sB)[48] = (float(*)[48])(smem + 4096);
        int m0 = (blockIdx.x & 31) * 64;
        int n0 = (blockIdx.x >> 5) * 48;
        int tx = t % 16, ty = t / 16;
        float acc[4][3] = {};
        int am = t >> 2, ak = (t & 3) * 4;

        for (int kt = 0; kt < NH; kt += 16) {
            float4 av = *reinterpret_cast<const float4*>(&g_base[(size_t)(m0 + am) * NH + kt + ak]);
            float4 bv = make_float4(0.f, 0.f, 0.f, 0.f);
            if (t < 192) bv = *reinterpret_cast<const float4*>(&W_a0[(size_t)(n0 + am) * NH + kt + ak]);
            __syncthreads();
            sA[ak+0][am] = av.x; sA[ak+1][am] = av.y; sA[ak+2][am] = av.z; sA[ak+3][am] = av.w;
            if (t < 192) { sB[ak+0][am] = bv.x; sB[ak+1][am] = bv.y; sB[ak+2][am] = bv.z; sB[ak+3][am] = bv.w; }
            __syncthreads();
            #pragma unroll
            for (int k = 0; k < 16; k++) {
                float a[4], bb[3];
                #pragma unroll
                for (int ii = 0; ii < 4; ii++) a[ii] = sA[k][ty*4 + ii];
                #pragma unroll
                for (int j = 0; j < 3; j++)  bb[j] = sB[k][tx*3 + j];
                #pragma unroll
                for (int ii = 0; ii < 4; ii++)
                    #pragma unroll
                    for (int j = 0; j < 3; j++)
                        acc[ii][j] += a[ii] * bb[j];
            }
        }
        #pragma unroll
        for (int ii = 0; ii < 4; ii++) {
            int m = m0 + ty*4 + ii;
            #pragma unroll
            for (int j = 0; j < 3; j++) {
                int n = n0 + tx*3 + j;
                g_actA_h[(size_t)m * KP + n] = __float2half(fmaxf(acc[ii][j] + b_a0[n], 0.0f));
            }
        }
        __syncthreads();
        __threadfence();
        if (t == 0) atomicAdd(&g_a0done, 1);
    } else if (blockIdx.x < ACT_BID0) {
        // ---------------- value head (fp32) --------------------------------
        float (*sbase)[NH] = (float(*)[NH])smem;
        float (*sv0)[32]   = (float(*)[32])(smem + 18432);
        int r0 = (blockIdx.x - A0_BLOCKS) * 8;
        for (int idx = t; idx < 8 * NH; idx += 256)
            sbase[idx / NH][idx % NH] = g_base[(size_t)(r0 + idx / NH) * NH + (idx % NH)];
        __syncthreads();

        int w = t / 32, lane = t % 32;
        const float* bp = sbase[w];

        float acc = b_v0[lane];
        const float* wp = g_WTv0 + lane;
        #pragma unroll 8
        for (int k = 0; k < NH; k++) acc += wp[(size_t)k * 32] * bp[k];
        sv0[w][lane] = fmaxf(acc, 0.0f);
        __syncwarp();

        float acc1 = b_v1[lane];
        #pragma unroll
        for (int j = 0; j < 32; j++) acc1 += W_v1[lane * 32 + j] * sv0[w][j];
        acc1 = fmaxf(acc1, 0.0f);

        float part = W_v2[lane] * acc1;
        for (int k = lane; k < NH; k += 32) part += W_vs[k] * bp[k];
        #pragma unroll
        for (int off = 16; off > 0; off >>= 1)
            part += __shfl_down_sync(0xffffffffu, part, off);
        if (lane == 0) out[r0 + w] = part + b_v2[0] + b_vs[0];
    } else {
        // ---------------- act GEMM (64x128, 4-ring, base-first K) ----------
        __half* sA   = (__half*)smem;
        __half* sB   = (__half*)(smem + NRING * ABUF);
        float* sBias = (float*)(smem + NRING * (ABUF + BBUF));

        int bid = blockIdx.x - ACT_BID0;
        int lane = t & 31, wid = t >> 5;
        int n0 = (bid & 31) * 128, m0 = (bid >> 5) * 64;
        int mbase = (wid >> 2) * 32;
        int nbase = (wid & 3) * 32;
        if (t < 128) sBias[t] = b_a1[n0 + t] + b_as[n0 + t];

        uint32_t saB = (uint32_t)__cvta_generic_to_shared(sA);
        uint32_t sbB = (uint32_t)__cvta_generic_to_shared(sB);

        int lrow = t >> 2, lg = t & 3;
        const __half* gA  = g_actA_h + (size_t)(m0 + lrow) * KP + lg * 8;
        const __half* gB0 = g_actB_h + (size_t)(n0 + lrow) * KP + lg * 8;
        const __half* gB1 = g_actB_h + (size_t)(n0 + lrow + 64) * KP + lg * 8;
        uint32_t dA  = saB + lrow * 80 + lg * 16;
        uint32_t dB0 = sbB + lrow * 80 + lg * 16;
        uint32_t dB1 = sbB + (lrow + 64) * 80 + lg * 16;

        int l7 = lane & 7;
        int aRow = mbase + ((lane >> 3) & 1) * 8 + l7;
        int aK   = (lane >> 4) & 1;
        int bRow = ((lane >> 4) & 1) * 8 + l7;
        int bK   = (lane >> 3) & 1;
        uint32_t aAddr[2], bAddr[2];
        #pragma unroll
        for (int mt = 0; mt < 2; mt++) aAddr[mt] = saB + (aRow + mt * 16) * 80 + aK * 16;
        #pragma unroll
        for (int p = 0; p < 2; p++)    bAddr[p]  = sbB + (nbase + p * 16 + bRow) * 80 + bK * 16;

        float acc[2][4][4] = {};

        #pragma unroll
        for (int s = 0; s < 3; s++) {
            int ko = act_koff(s);
            CP16(dA  + s * ABUF, gA  + ko);
            CP16(dB0 + s * BBUF, gB0 + ko);
            CP16(dB1 + s * BBUF, gB1 + ko);
            CPCOMMIT();
        }

        for (int s = 0; s < NSTG; s++) {
            if (s + 3 <= NSTG)      { CPWAIT(2); }
            else if (s + 2 == NSTG) { CPWAIT(1); }
            else                    { CPWAIT(0); }
            __syncthreads();

            if (s + 3 < NSTG) {
                if (s + 3 == 18) {          // first a0 chunk: wait for a0 blocks
                    if (t == 0) {
                        while (atomicAdd(&g_a0done, 0) < A0_BLOCKS) { }
                    }
                    __syncthreads();
                }
                int nb = (s + 3) % NRING;
                int ko = act_koff(s + 3);
                CP16(dA  + nb * ABUF, gA  + ko);
                CP16(dB0 + nb * BBUF, gB0 + ko);
                CP16(dB1 + nb * BBUF, gB1 + ko);
                CPCOMMIT();
            }

            uint32_t boA = (s % NRING) * ABUF;
            uint32_t boB = (s % NRING) * BBUF;
            #pragma unroll
            for (int ks = 0; ks < 2; ks++) {
                uint32_t kb = ks * 32;
                uint32_t afr[2][4];
                #pragma unroll
                for (int mt = 0; mt < 2; mt++) LDSM4(afr[mt], aAddr[mt] + boA + kb);
                uint32_t bfr[4][2];
                #pragma unroll
                for (int p = 0; p < 2; p++) {
                    uint32_t r[4];
                    LDSM4(r, bAddr[p] + boB + kb);
                    bfr[2*p][0]   = r[0]; bfr[2*p][1]   = r[1];
                    bfr[2*p+1][0] = r[2]; bfr[2*p+1][1] = r[3];
                }
                #pragma unroll
                for (int mt = 0; mt < 2; mt++)
                    #pragma unroll
                    for (int nt = 0; nt < 4; nt++) {
                        asm volatile(
                            "mma.sync.aligned.m16n8k16.row.col.f32.f16.f16.f32 "
                            "{%0,%1,%2,%3}, {%4,%5,%6,%7}, {%8,%9}, {%0,%1,%2,%3};\n"
                            : "+f"(acc[mt][nt][0]), "+f"(acc[mt][nt][1]),
                              "+f"(acc[mt][nt][2]), "+f"(acc[mt][nt][3])
                            : "r"(afr[mt][0]), "r"(afr[mt][1]),
                              "r"(afr[mt][2]), "r"(afr[mt][3]),
                              "r"(bfr[nt][0]), "r"(bfr[nt][1]));
                    }
            }
        }

        int r4 = lane >> 2, c4 = lane & 3;
        #pragma unroll
        for (int mt = 0; mt < 2; mt++) {
            int m = m0 + mbase + mt * 16 + r4;
            #pragma unroll
            for (int nt = 0; nt < 4; nt++) {
                int nl = nbase + nt * 8 + 2 * c4;
                float bi0 = sBias[nl], bi1 = sBias[nl + 1];
                float2 v0 = make_float2(acc[mt][nt][0] + bi0, acc[mt][nt][1] + bi1);
                float2 v1 = make_float2(acc[mt][nt][2] + bi0, acc[mt][nt][3] + bi1);
                __stcs((float2*)&out[NB + (size_t)m       * NMOVE + n0 + nl], v0);
                __stcs((float2*)&out[NB + (size_t)(m + 8) * NMOVE + n0 + nl], v1);
            }
        }
    }
}

extern "C" void kernel_launch(void* const* d_in, const int* in_sizes, int n_in,
                              void* d_out, int out_size)
{
    const float* pov   = (const float*)d_in[0];
    const float* white = (const float*)d_in[1];
    const float* black = (const float*)d_in[2];
    const float* W_w   = (const float*)d_in[3];
    const float* b_w   = (const float*)d_in[4];
    const float* W_b   = (const float*)d_in[5];
    const float* b_b   = (const float*)d_in[6];
    const float* W_v0  = (const float*)d_in[7];
    const float* b_v0  = (const float*)d_in[8];
    const float* W_v1  = (const float*)d_in[9];
    const float* b_v1  = (const float*)d_in[10];
    const float* W_v2  = (const float*)d_in[11];
    const float* b_v2  = (const float*)d_in[12];
    const float* W_a0  = (const float*)d_in[13];
    const float* b_a0  = (const float*)d_in[14];
    const float* W_a1  = (const float*)d_in[15];
    const float* b_a1  = (const float*)d_in[16];
    const float* W_vs  = (const float*)d_in[17];
    const float* b_vs  = (const float*)d_in[18];
    const float* W_as  = (const float*)d_in[19];
    const float* b_as  = (const float*)d_in[20];
    float* out = (float*)d_out;

    cudaFuncSetAttribute(fuse_kernel,
                         cudaFuncAttributeMaxDynamicSharedMemorySize, SM_FUSE);

    prep_kernel<<<PREP_BLOCKS, 256>>>(white, black, W_w, W_b, W_v0, W_a1, W_as,
                                      pov, b_w, b_b);
    fuse_kernel<<<ACT_BID0 + (NMOVE / 128) * (NB / 64), 256, SM_FUSE>>>(
        W_a0, b_a0, b_v0, W_v1, b_v1, W_v2, b_v2, W_vs, b_vs, b_a1, b_as, out);
}

// round 16
// speedup vs baseline: 1.1088x; 1.1088x over previous
#include <cuda_runtime.h>
#include <cuda_fp16.h>
#include <cstdint>

#define NB    2048
#define ND    40960
#define NBASE 288
#define NH    576     // 2*NBASE
#define NA0   144
#define NMOVE 4096
#define KP    736     // padded act K: [a0(144) pad(16) base(576)]
#define AOFF  160     // base starts here
#define NSTG  23      // K chunks of 32 halfs (64B rows)
#define MAXNZ 512

// -------- device scratch (no allocations allowed) --------
__device__ __half g_WTw_h[(size_t)ND * NBASE]; // W_w^T  [D, 288] fp16
__device__ __half g_WTb_h[(size_t)ND * NBASE]; // W_b^T  [D, 288] fp16
__device__ float  g_WTv0[NH * 32];             // W_v0^T [576, 32] fp32
__device__ float  g_base[(size_t)NB * NH];     // relu'd base, fp32
__device__ __half g_actA_h[(size_t)NB * KP];   // [relu(a0) | 0 | relu(base)] fp16
__device__ __half g_actB_h[(size_t)NMOVE * KP];// [W_a1 | 0 | W_as] fp16
__device__ int    g_nzcnt[NB * 2];
__device__ int    g_nzidx[(size_t)NB * 2 * MAXNZ];
__device__ int    g_a0done;                    // a0-blocks completion counter

#define CP16(dst, src) asm volatile("cp.async.cg.shared.global [%0], [%1], 16;" :: "r"(dst), "l"(src))
#define CPCOMMIT()     asm volatile("cp.async.commit_group;")
#define CPWAIT(n)      asm volatile("cp.async.wait_group %0;" :: "n"(n))
#define LDSM4(R, addr) asm volatile( \
    "ldmatrix.sync.aligned.m8n8.x4.shared.b16 {%0,%1,%2,%3}, [%4];" \
    : "=r"((R)[0]), "=r"((R)[1]), "=r"((R)[2]), "=r"((R)[3]) : "r"(addr))

// ============== mega prep kernel: scan + transposes + bprep ================
// Block ranges (256 threads each):
//   [0, 4096)          : mask scan (indices only — nonzeros are exactly 1.0)
//   [4096, 27136)      : transpose W_w / W_b -> fp16
//   [27136, 31232)     : bprep (g_actB_h)
//   [31232, 31250)     : W_v0 transpose (fp32)
#define NSCAN  (NB * 2)
#define NTRB   ((ND / 32) * (NBASE / 32))     // 11520 per matrix
#define BP_BID0 (NSCAN + 2 * NTRB)            // 27136
#define WV_BID0 (BP_BID0 + NMOVE)             // 31232
#define PREP_BLOCKS (WV_BID0 + NH / 32)       // 31250

#define CHECKI(vv, uu) do { \
    if ((vv).x != 0.0f) { int p = atomicAdd(s_cnt, 1); if (p < MAXNZ) s_idx[p] = 4*(uu)+0; } \
    if ((vv).y != 0.0f) { int p = atomicAdd(s_cnt, 1); if (p < MAXNZ) s_idx[p] = 4*(uu)+1; } \
    if ((vv).z != 0.0f) { int p = atomicAdd(s_cnt, 1); if (p < MAXNZ) s_idx[p] = 4*(uu)+2; } \
    if ((vv).w != 0.0f) { int p = atomicAdd(s_cnt, 1); if (p < MAXNZ) s_idx[p] = 4*(uu)+3; } \
} while (0)

__global__ __launch_bounds__(256) void prep_kernel(
    const float* __restrict__ white, const float* __restrict__ black,
    const float* __restrict__ W_w,   const float* __restrict__ W_b,
    const float* __restrict__ W_v0,
    const float* __restrict__ W_a1,  const float* __restrict__ W_as)
{
    __shared__ __align__(16) char shbuf[4352];
    int bi = blockIdx.x;
    int t  = threadIdx.x;
    if (bi == 0 && t == 0) g_a0done = 0;    // reset spin counter each launch

    if (bi < NSCAN) {
        // ---- mask scan: 4 independent streaming loads in flight ----
        int* s_idx = (int*)shbuf;
        int* s_cnt = (int*)(shbuf + 2048);
        int b = bi >> 1, h = bi & 1;
        if (t == 0) *s_cnt = 0;
        __syncthreads();
        const float* src = h ? black : white;
        const float4* row = reinterpret_cast<const float4*>(src + (size_t)b * ND);
        #pragma unroll 1
        for (int u = t; u < ND / 4; u += 1024) {   // 10240 = 10 * 1024
            float4 v0 = __ldcs(&row[u]);
            float4 v1 = __ldcs(&row[u + 256]);
            float4 v2 = __ldcs(&row[u + 512]);
            float4 v3 = __ldcs(&row[u + 768]);
            CHECKI(v0, u);
            CHECKI(v1, u + 256);
            CHECKI(v2, u + 512);
            CHECKI(v3, u + 768);
        }
        __syncthreads();
        int n = *s_cnt;
        if (n > MAXNZ) n = MAXNZ;
        if (t == 0) g_nzcnt[bi] = n;
        for (int k = t; k < n; k += 256)
            g_nzidx[(size_t)bi * MAXNZ + k] = s_idx[k];
    } else if (bi < BP_BID0) {
        // ---- big transposes fp32 -> fp16 ----
        int which = (bi - NSCAN) / NTRB;
        int idx   = (bi - NSCAN) % NTRB;
        int c0 = (idx % (ND / 32)) * 32;
        int r0 = (idx / (ND / 32)) * 32;
        const float* in = which ? W_b : W_w;
        __half* outp = which ? g_WTb_h : g_WTw_h;
        float (*tile)[33] = (float(*)[33])shbuf;
        int x = t & 31, y = t >> 5;
        #pragma unroll
        for (int yy = y; yy < 32; yy += 8)
            tile[yy][x] = in[(size_t)(r0 + yy) * ND + c0 + x];
        __syncthreads();
        #pragma unroll
        for (int yy = y; yy < 32; yy += 8)
            outp[(size_t)(c0 + yy) * NBASE + r0 + x] = __float2half(tile[x][yy]);
    } else if (bi < WV_BID0) {
        // ---- bprep ----
        int n = bi - BP_BID0;
        for (int c2 = t; c2 < KP / 2; c2 += 256) {
            int c = c2 * 2;
            float v0 = 0.0f, v1 = 0.0f;
            if (c < NA0) {
                const float2 w = *(const float2*)&W_a1[(size_t)n * NA0 + c];
                v0 = w.x; v1 = w.y;
            } else if (c >= AOFF) {
                const float2 w = *(const float2*)&W_as[(size_t)n * NH + (c - AOFF)];
                v0 = w.x; v1 = w.y;
            }
            *(__half2*)&g_actB_h[(size_t)n * KP + c] = __floats2half2_rn(v0, v1);
        }
    } else {
        // ---- W_v0 transpose fp32 ----
        int idx = bi - WV_BID0;
        int c0 = idx * 32;
        float (*tile)[33] = (float(*)[33])shbuf;
        int x = t & 31, y = t >> 5;
        #pragma unroll
        for (int yy = y; yy < 32; yy += 8)
            tile[yy][x] = W_v0[(size_t)yy * NH + c0 + x];
        __syncthreads();
        #pragma unroll
        for (int yy = y; yy < 32; yy += 8)
            g_WTv0[(size_t)(c0 + yy) * 32 + x] = tile[x][yy];
    }
}

// ======= gather: sum of WT rows (nz values are exactly 1.0) ================
__global__ __launch_bounds__(NBASE) void gather_kernel(
    const float* __restrict__ pov,
    const float* __restrict__ b_w, const float* __restrict__ b_b)
{
    __shared__ int s_idx[MAXNZ];
    int bi = blockIdx.x;
    int b = bi >> 1, h = bi & 1;
    int i = threadIdx.x;
    if (h == 0 && i < 16) g_actA_h[(size_t)b * KP + NA0 + i] = __float2half(0.0f);

    int n = g_nzcnt[bi];
    if (n > MAXNZ) n = MAXNZ;
    for (int k = i; k < n; k += NBASE)
        s_idx[k] = g_nzidx[(size_t)bi * MAXNZ + k];
    __syncthreads();

    const __half* WT = h ? g_WTb_h : g_WTw_h;
    float acc = h ? b_b[i] : b_w[i];
    int k = 0;
    for (; k + 8 <= n; k += 8) {
        float p0 = __half2float(WT[(size_t)s_idx[k+0] * NBASE + i]);
        float p1 = __half2float(WT[(size_t)s_idx[k+1] * NBASE + i]);
        float p2 = __half2float(WT[(size_t)s_idx[k+2] * NBASE + i]);
        float p3 = __half2float(WT[(size_t)s_idx[k+3] * NBASE + i]);
        float p4 = __half2float(WT[(size_t)s_idx[k+4] * NBASE + i]);
        float p5 = __half2float(WT[(size_t)s_idx[k+5] * NBASE + i]);
        float p6 = __half2float(WT[(size_t)s_idx[k+6] * NBASE + i]);
        float p7 = __half2float(WT[(size_t)s_idx[k+7] * NBASE + i]);
        acc += ((p0 + p1) + (p2 + p3)) + ((p4 + p5) + (p6 + p7));
    }
    for (; k < n; k++)
        acc += __half2float(WT[(size_t)s_idx[k] * NBASE + i]);

    float pv = pov[b];
    int pos;
    if (h == 0) pos = (pv > 0.5f) ? i : (NBASE + i);
    else        pos = (pv > 0.5f) ? (NBASE + i) : i;
    float r = fmaxf(acc, 0.0f);
    g_base[(size_t)b * NH + pos] = r;
    g_actA_h[(size_t)b * KP + AOFF + pos] = __float2half(r);
}

// ======== fused a0 + value + act (block-range dispatch, spin-sync) =========
// bids [0,96): a0   [96,352): value   [352,1376): act (flattened 32n x 32m)
// act K order: base chunks first (18), a0 chunks last (5) — spin on g_a0done.
#define A0_BLOCKS  96
#define VAL_BLOCKS 256
#define ACT_BID0   (A0_BLOCKS + VAL_BLOCKS)
#define ABUF   (64 * 80)
#define BBUF   (128 * 80)
#define NRING  4
#define SM_FUSE (NRING * (ABUF + BBUF) + 512)   // 61952 bytes

__device__ __forceinline__ int act_koff(int s) {    // stage -> half offset
    return (s < 18) ? (AOFF + s * 32) : ((s - 18) * 32);
}

__global__ __launch_bounds__(256, 3) void fuse_kernel(
    const float* __restrict__ W_a0, const float* __restrict__ b_a0,
    const float* __restrict__ b_v0,
    const float* __restrict__ W_v1, const float* __restrict__ b_v1,
    const float* __restrict__ W_v2, const float* __restrict__ b_v2,
    const float* __restrict__ W_vs, const float* __restrict__ b_vs,
    const float* __restrict__ b_a1, const float* __restrict__ b_as,
    float* __restrict__ out)
{
    extern __shared__ __align__(16) char smem[];
    int t = threadIdx.x;

    if (blockIdx.x < A0_BLOCKS) {
        // ---------------- a0 = relu(base @ W_a0^T + b_a0) -> fp16 ----------
        float (*sA)[64] = (float(*)[64])smem;
        float (*sB)[48] = (float(*)[48])(smem + 4096);
        int m0 = (blockIdx.x & 31) * 64;
        int n0 = (blockIdx.x >> 5) * 48;
        int tx = t % 16, ty = t / 16;
        float acc[4][3] = {};
        int am = t >> 2, ak = (t & 3) * 4;

        for (int kt = 0; kt < NH; kt += 16) {
            float4 av = *reinterpret_cast<const float4*>(&g_base[(size_t)(m0 + am) * NH + kt + ak]);
            float4 bv = make_float4(0.f, 0.f, 0.f, 0.f);
            if (t < 192) bv = *reinterpret_cast<const float4*>(&W_a0[(size_t)(n0 + am) * NH + kt + ak]);
            __syncthreads();
            sA[ak+0][am] = av.x; sA[ak+1][am] = av.y; sA[ak+2][am] = av.z; sA[ak+3][am] = av.w;
            if (t < 192) { sB[ak+0][am] = bv.x; sB[ak+1][am] = bv.y; sB[ak+2][am] = bv.z; sB[ak+3][am] = bv.w; }
            __syncthreads();
            #pragma unroll
            for (int k = 0; k < 16; k++) {
                float a[4], bb[3];
                #pragma unroll
                for (int ii = 0; ii < 4; ii++) a[ii] = sA[k][ty*4 + ii];
                #pragma unroll
                for (int j = 0; j < 3; j++)  bb[j] = sB[k][tx*3 + j];
                #pragma unroll
                for (int ii = 0; ii < 4; ii++)
                    #pragma unroll
                    for (int j = 0; j < 3; j++)
                        acc[ii][j] += a[ii] * bb[j];
            }
        }
        #pragma unroll
        for (int ii = 0; ii < 4; ii++) {
            int m = m0 + ty*4 + ii;
            #pragma unroll
            for (int j = 0; j < 3; j++) {
                int n = n0 + tx*3 + j;
                g_actA_h[(size_t)m * KP + n] = __float2half(fmaxf(acc[ii][j] + b_a0[n], 0.0f));
            }
        }
        __syncthreads();
        __threadfence();
        if (t == 0) atomicAdd(&g_a0done, 1);
    } else if (blockIdx.x < ACT_BID0) {
        // ---------------- value head (fp32) --------------------------------
        float (*sbase)[NH] = (float(*)[NH])smem;
        float (*sv0)[32]   = (float(*)[32])(smem + 18432);
        int r0 = (blockIdx.x - A0_BLOCKS) * 8;
        for (int idx = t; idx < 8 * NH; idx += 256)
            sbase[idx / NH][idx % NH] = g_base[(size_t)(r0 + idx / NH) * NH + (idx % NH)];
        __syncthreads();

        int w = t / 32, lane = t % 32;
        const float* bp = sbase[w];

        float acc = b_v0[lane];
        const float* wp = g_WTv0 + lane;
        #pragma unroll 8
        for (int k = 0; k < NH; k++) acc += wp[(size_t)k * 32] * bp[k];
        sv0[w][lane] = fmaxf(acc, 0.0f);
        __syncwarp();

        float acc1 = b_v1[lane];
        #pragma unroll
        for (int j = 0; j < 32; j++) acc1 += W_v1[lane * 32 + j] * sv0[w][j];
        acc1 = fmaxf(acc1, 0.0f);

        float part = W_v2[lane] * acc1;
        for (int k = lane; k < NH; k += 32) part += W_vs[k] * bp[k];
        #pragma unroll
        for (int off = 16; off > 0; off >>= 1)
            part += __shfl_down_sync(0xffffffffu, part, off);
        if (lane == 0) out[r0 + w] = part + b_v2[0] + b_vs[0];
    } else {
        // ---------------- act GEMM (64x128, 4-ring, base-first K) ----------
        __half* sA   = (__half*)smem;
        __half* sB   = (__half*)(smem + NRING * ABUF);
        float* sBias = (float*)(smem + NRING * (ABUF + BBUF));

        int bid = blockIdx.x - ACT_BID0;
        int lane = t & 31, wid = t >> 5;
        int n0 = (bid & 31) * 128, m0 = (bid >> 5) * 64;
        int mbase = (wid >> 2) * 32;
        int nbase = (wid & 3) * 32;
        if (t < 128) sBias[t] = b_a1[n0 + t] + b_as[n0 + t];

        uint32_t saB = (uint32_t)__cvta_generic_to_shared(sA);
        uint32_t sbB = (uint32_t)__cvta_generic_to_shared(sB);

        int lrow = t >> 2, lg = t & 3;
        const __half* gA  = g_actA_h + (size_t)(m0 + lrow) * KP + lg * 8;
        const __half* gB0 = g_actB_h + (size_t)(n0 + lrow) * KP + lg * 8;
        const __half* gB1 = g_actB_h + (size_t)(n0 + lrow + 64) * KP + lg * 8;
        uint32_t dA  = saB + lrow * 80 + lg * 16;
        uint32_t dB0 = sbB + lrow * 80 + lg * 16;
        uint32_t dB1 = sbB + (lrow + 64) * 80 + lg * 16;

        int l7 = lane & 7;
        int aRow = mbase + ((lane >> 3) & 1) * 8 + l7;
        int aK   = (lane >> 4) & 1;
        int bRow = ((lane >> 4) & 1) * 8 + l7;
        int bK   = (lane >> 3) & 1;
        uint32_t aAddr[2], bAddr[2];
        #pragma unroll
        for (int mt = 0; mt < 2; mt++) aAddr[mt] = saB + (aRow + mt * 16) * 80 + aK * 16;
        #pragma unroll
        for (int p = 0; p < 2; p++)    bAddr[p]  = sbB + (nbase + p * 16 + bRow) * 80 + bK * 16;

        float acc[2][4][4] = {};

        #pragma unroll
        for (int s = 0; s < 3; s++) {
            int ko = act_koff(s);
            CP16(dA  + s * ABUF, gA  + ko);
            CP16(dB0 + s * BBUF, gB0 + ko);
            CP16(dB1 + s * BBUF, gB1 + ko);
            CPCOMMIT();
        }

        for (int s = 0; s < NSTG; s++) {
            if (s + 3 <= NSTG)      { CPWAIT(2); }
            else if (s + 2 == NSTG) { CPWAIT(1); }
            else                    { CPWAIT(0); }
            __syncthreads();

            if (s + 3 < NSTG) {
                if (s + 3 == 18) {          // first a0 chunk: wait for a0 blocks
                    if (t == 0) {
                        while (atomicAdd(&g_a0done, 0) < A0_BLOCKS) { }
                    }
                    __syncthreads();
                }
                int nb = (s + 3) % NRING;
                int ko = act_koff(s + 3);
                CP16(dA  + nb * ABUF, gA  + ko);
                CP16(dB0 + nb * BBUF, gB0 + ko);
                CP16(dB1 + nb * BBUF, gB1 + ko);
                CPCOMMIT();
            }

            uint32_t boA = (s % NRING) * ABUF;
            uint32_t boB = (s % NRING) * BBUF;
            #pragma unroll
            for (int ks = 0; ks < 2; ks++) {
                uint32_t kb = ks * 32;
                uint32_t afr[2][4];
                #pragma unroll
                for (int mt = 0; mt < 2; mt++) LDSM4(afr[mt], aAddr[mt] + boA + kb);
                uint32_t bfr[4][2];
                #pragma unroll
                for (int p = 0; p < 2; p++) {
                    uint32_t r[4];
                    LDSM4(r, bAddr[p] + boB + kb);
                    bfr[2*p][0]   = r[0]; bfr[2*p][1]   = r[1];
                    bfr[2*p+1][0] = r[2]; bfr[2*p+1][1] = r[3];
                }
                #pragma unroll
                for (int mt = 0; mt < 2; mt++)
                    #pragma unroll
                    for (int nt = 0; nt < 4; nt++) {
                        asm volatile(
                            "mma.sync.aligned.m16n8k16.row.col.f32.f16.f16.f32 "
                            "{%0,%1,%2,%3}, {%4,%5,%6,%7}, {%8,%9}, {%0,%1,%2,%3};\n"
                            : "+f"(acc[mt][nt][0]), "+f"(acc[mt][nt][1]),
                              "+f"(acc[mt][nt][2]), "+f"(acc[mt][nt][3])
                            : "r"(afr[mt][0]), "r"(afr[mt][1]),
                              "r"(afr[mt][2]), "r"(afr[mt][3]),
                              "r"(bfr[nt][0]), "r"(bfr[nt][1]));
                    }
            }
        }

        int r4 = lane >> 2, c4 = lane & 3;
        #pragma unroll
        for (int mt = 0; mt < 2; mt++) {
            int m = m0 + mbase + mt * 16 + r4;
            #pragma unroll
            for (int nt = 0; nt < 4; nt++) {
                int nl = nbase + nt * 8 + 2 * c4;
                float bi0 = sBias[nl], bi1 = sBias[nl + 1];
                float2 v0 = make_float2(acc[mt][nt][0] + bi0, acc[mt][nt][1] + bi1);
                float2 v1 = make_float2(acc[mt][nt][2] + bi0, acc[mt][nt][3] + bi1);
                __stcs((float2*)&out[NB + (size_t)m       * NMOVE + n0 + nl], v0);
                __stcs((float2*)&out[NB + (size_t)(m + 8) * NMOVE + n0 + nl], v1);
            }
        }
    }
}

extern "C" void kernel_launch(void* const* d_in, const int* in_sizes, int n_in,
                              void* d_out, int out_size)
{
    const float* pov   = (const float*)d_in[0];
    const float* white = (const float*)d_in[1];
    const float* black = (const float*)d_in[2];
    const float* W_w   = (const float*)d_in[3];
    const float* b_w   = (const float*)d_in[4];
    const float* W_b   = (const float*)d_in[5];
    const float* b_b   = (const float*)d_in[6];
    const float* W_v0  = (const float*)d_in[7];
    const float* b_v0  = (const float*)d_in[8];
    const float* W_v1  = (const float*)d_in[9];
    const float* b_v1  = (const float*)d_in[10];
    const float* W_v2  = (const float*)d_in[11];
    const float* b_v2  = (const float*)d_in[12];
    const float* W_a0  = (const float*)d_in[13];
    const float* b_a0  = (const float*)d_in[14];
    const float* W_a1  = (const float*)d_in[15];
    const float* b_a1  = (const float*)d_in[16];
    const float* W_vs  = (const float*)d_in[17];
    const float* b_vs  = (const float*)d_in[18];
    const float* W_as  = (const float*)d_in[19];
    const float* b_as  = (const float*)d_in[20];
    float* out = (float*)d_out;

    cudaFuncSetAttribute(fuse_kernel,
                         cudaFuncAttributeMaxDynamicSharedMemorySize, SM_FUSE);

    prep_kernel<<<PREP_BLOCKS, 256>>>(white, black, W_w, W_b, W_v0, W_a1, W_as);
    gather_kernel<<<NB * 2, NBASE>>>(pov, b_w, b_b);
    fuse_kernel<<<ACT_BID0 + (NMOVE / 128) * (NB / 64), 256, SM_FUSE>>>(
        W_a0, b_a0, b_v0, W_v1, b_v1, W_v2, b_v2, W_vs, b_vs, b_a1, b_as, out);
}